// round 1
// baseline (speedup 1.0000x reference)
#include <cuda_runtime.h>

// Problem constants (fixed by reference)
#define NC       10000
#define ND       1000000
#define B        8192
#define K        64
#define EMB      16
#define CH_DENSE 16
#define DEV_DENSE 20
#define H1       64
#define H2       64
#define ATTN_H   84
#define IN1      32      // CH_DENSE + EMB
#define IN2      132     // DEV_DENSE + 7*EMB

// Scratch: aggregated+projected neighbor features, [2, B, H2]
__device__ float g_h[2 * B * H2];

// ---------------------------------------------------------------------------
// Kernel A: per (vertex, side) aggregation + W_agg projection
//   grid = (B, 2), block = 160 threads
// ---------------------------------------------------------------------------
__global__ __launch_bounds__(160)
void agg_kernel(const float* __restrict__ device_dense,   // [ND, 20]
                const int*   __restrict__ device_cat,     // [ND, 7]
                const float* __restrict__ lang_emb,
                const float* __restrict__ plat_emb,
                const float* __restrict__ os_emb,
                const float* __restrict__ country_emb,
                const float* __restrict__ carrier_emb,
                const float* __restrict__ brand_emb,
                const float* __restrict__ plat_os_emb,
                const float* __restrict__ W_agg,          // [132, 64]
                const float* __restrict__ b_agg,          // [64]
                const int*   __restrict__ bot_neibrs,     // [B, K]
                const int*   __restrict__ normal_neibrs,  // [B, K]
                const int*   __restrict__ bot_counts,     // [B]
                const int*   __restrict__ normal_counts)  // [B]
{
    const int b    = blockIdx.x;
    const int side = blockIdx.y;
    const int t    = threadIdx.x;

    __shared__ int   s_nb[K];
    __shared__ int   s_cat[K * 7];
    __shared__ float s_dense[K * DEV_DENSE];
    __shared__ float s_mean[IN2];

    const int* __restrict__ neibrs = side ? normal_neibrs : bot_neibrs;
    const int* __restrict__ counts = side ? normal_counts : bot_counts;

    int cnt = counts[b];
    cnt = cnt < 1 ? 1 : (cnt > K ? K : cnt);

    // Phase 1: neighbor indices
    if (t < K) s_nb[t] = neibrs[b * K + t];
    __syncthreads();

    // Phase 2: cooperative gather of cat rows and dense rows (independent loads, high MLP)
    for (int i = t; i < cnt * 7; i += 160) {
        int k = i / 7, j = i - k * 7;
        s_cat[i] = device_cat[(long)s_nb[k] * 7 + j];
    }
    for (int i = t; i < cnt * DEV_DENSE; i += 160) {
        int k = i / DEV_DENSE, j = i - k * DEV_DENSE;
        s_dense[i] = device_dense[(long)s_nb[k] * DEV_DENSE + j];
    }
    __syncthreads();

    // Phase 3: masked sum over neighbors; thread t owns feature dim t (t < 132)
    if (t < IN2) {
        float acc = 0.f;
        if (t < DEV_DENSE) {
            #pragma unroll 4
            for (int k = 0; k < cnt; ++k) acc += s_dense[k * DEV_DENSE + t];
        } else {
            const int j = (t - DEV_DENSE) >> 4;   // which cat table
            const int e = (t - DEV_DENSE) & 15;   // element within embedding
            const float* __restrict__ tab;
            switch (j) {
                case 0: tab = lang_emb;    break;
                case 1: tab = plat_emb;    break;
                case 2: tab = os_emb;      break;
                case 3: tab = country_emb; break;
                case 4: tab = carrier_emb; break;
                case 5: tab = brand_emb;   break;
                default: tab = plat_os_emb; break;
            }
            #pragma unroll 4
            for (int k = 0; k < cnt; ++k) {
                int c = s_cat[k * 7 + j];
                acc += tab[c * EMB + e];
            }
        }
        s_mean[t] = acc / (float)cnt;
    }
    __syncthreads();

    // Phase 4: h = mean @ W_agg + b_agg   (64 output cols, one per thread)
    if (t < H2) {
        float acc = b_agg[t];
        #pragma unroll 4
        for (int i = 0; i < IN2; ++i)
            acc = fmaf(s_mean[i], W_agg[i * H2 + t], acc);
        g_h[((long)side * B + b) * H2 + t] = acc;
    }
}

// ---------------------------------------------------------------------------
// Kernel B: per-vertex attention MLP + softmax(2) + combine + self-linear
//   grid = B, block = 256 threads
// ---------------------------------------------------------------------------
__global__ __launch_bounds__(256)
void finalize_kernel(const float* __restrict__ channel_dense,  // [NC, 16]
                     const float* __restrict__ channel_id_emb, // [NC, 16]
                     const float* __restrict__ W_self,         // [32, 64]
                     const float* __restrict__ b_self,         // [64]
                     const float* __restrict__ W_attn,         // [96, 84]
                     const float* __restrict__ b_attn,         // [84]
                     const float* __restrict__ W_attn2,        // [84, 1]
                     const float* __restrict__ b_attn2,        // [1]
                     const int*   __restrict__ channel_ids,    // [NC]
                     const int*   __restrict__ vertices,       // [B]
                     float*       __restrict__ out)            // [B, 128]
{
    const int b = blockIdx.x;
    const int t = threadIdx.x;

    __shared__ float s_chv[IN1];
    __shared__ float s_hb[H2];
    __shared__ float s_hn[H2];
    __shared__ float s_red[2][ATTN_H];
    __shared__ float s_sc[2];

    const int v = vertices[b];

    if (t < CH_DENSE) {
        s_chv[t] = channel_dense[(long)v * CH_DENSE + t];
    } else if (t < IN1) {
        int cid = channel_ids[v];
        s_chv[t] = channel_id_emb[(long)cid * EMB + (t - CH_DENSE)];
    } else if (t < IN1 + H2) {
        s_hb[t - IN1] = g_h[(long)b * H2 + (t - IN1)];
    } else if (t < IN1 + 2 * H2) {
        s_hn[t - IN1 - H2] = g_h[((long)B + b) * H2 + (t - IN1 - H2)];
    }
    __syncthreads();

    // Attention hidden: group g (0 = bots, 1 = normal), 84 active lanes each
    const int g  = t >> 7;
    const int lt = t & 127;
    if (lt < ATTN_H) {
        const float* __restrict__ h = g ? s_hn : s_hb;
        float acc = b_attn[lt];
        #pragma unroll 4
        for (int i = 0; i < H2; ++i)
            acc = fmaf(h[i], W_attn[i * ATTN_H + lt], acc);
        #pragma unroll 4
        for (int i = 0; i < IN1; ++i)
            acc = fmaf(s_chv[i], W_attn[(H2 + i) * ATTN_H + lt], acc);
        s_red[g][lt] = fmaxf(acc, 0.f) * W_attn2[lt];
    }
    __syncthreads();

    if (t < 2) {
        float s = b_attn2[0];
        #pragma unroll 4
        for (int i = 0; i < ATTN_H; ++i) s += s_red[t][i];
        s_sc[t] = s;
    }
    __syncthreads();

    const float m  = fmaxf(s_sc[0], s_sc[1]);
    const float e0 = expf(s_sc[0] - m);
    const float e1 = expf(s_sc[1] - m);
    const float inv = 1.f / (e0 + e1);
    const float a0 = e0 * inv, a1 = e1 * inv;

    if (t < H2) {
        out[(long)b * (H2 + H1) + t] = fmaxf(a0 * s_hb[t] + a1 * s_hn[t], 0.f);
    } else if (t < H2 + H1) {
        const int c = t - H2;
        float acc = b_self[c];
        #pragma unroll 4
        for (int i = 0; i < IN1; ++i)
            acc = fmaf(s_chv[i], W_self[i * H1 + c], acc);
        out[(long)b * (H2 + H1) + t] = fmaxf(acc, 0.f);
    }
}

// ---------------------------------------------------------------------------
extern "C" void kernel_launch(void* const* d_in, const int* in_sizes, int n_in,
                              void* d_out, int out_size)
{
    const float* channel_dense  = (const float*)d_in[0];
    const float* device_dense   = (const float*)d_in[1];
    const float* channel_id_emb = (const float*)d_in[2];
    const float* lang_emb       = (const float*)d_in[3];
    const float* plat_emb       = (const float*)d_in[4];
    const float* os_emb         = (const float*)d_in[5];
    const float* country_emb    = (const float*)d_in[6];
    const float* carrier_emb    = (const float*)d_in[7];
    const float* brand_emb      = (const float*)d_in[8];
    const float* plat_os_emb    = (const float*)d_in[9];
    const float* W_agg          = (const float*)d_in[10];
    const float* b_agg          = (const float*)d_in[11];
    const float* W_self         = (const float*)d_in[12];
    const float* b_self         = (const float*)d_in[13];
    const float* W_attn         = (const float*)d_in[14];
    const float* b_attn         = (const float*)d_in[15];
    const float* W_attn2        = (const float*)d_in[16];
    const float* b_attn2        = (const float*)d_in[17];
    const int*   channel_ids    = (const int*)d_in[18];
    const int*   device_cat     = (const int*)d_in[19];
    const int*   vertices       = (const int*)d_in[20];
    const int*   bot_neibrs     = (const int*)d_in[21];
    const int*   normal_neibrs  = (const int*)d_in[22];
    const int*   bot_counts     = (const int*)d_in[23];
    const int*   normal_counts  = (const int*)d_in[24];

    float* out = (float*)d_out;

    dim3 gridA(B, 2);
    agg_kernel<<<gridA, 160>>>(device_dense, device_cat,
                               lang_emb, plat_emb, os_emb, country_emb,
                               carrier_emb, brand_emb, plat_os_emb,
                               W_agg, b_agg,
                               bot_neibrs, normal_neibrs,
                               bot_counts, normal_counts);

    finalize_kernel<<<B, 256>>>(channel_dense, channel_id_emb,
                                W_self, b_self, W_attn, b_attn,
                                W_attn2, b_attn2,
                                channel_ids, vertices, out);
}